// round 10
// baseline (speedup 1.0000x reference)
#include <cuda_runtime.h>
#include <cuda_fp16.h>
#include <mma.h>
#include <cstdint>

using namespace nvcuda;

// Problem constants
#define B_DIM      32
#define S_DIM      2048
#define H_DIM      4096
#define R_DIM      64
#define N_ADAPT    16
#define TILE_M     128
#define KC         128                 // K elements per chunk (was 64)
#define NCHUNK     (H_DIM / KC)        // 32
#define NTHREADS   256

// SMEM (half): row stride 136 halves = 272 B.
//  - ldm multiple of 8 halves ✓
//  - 272*r mod 128 = 16r mod 128 distinct for r=0..7 -> conflict-free
#define LDH        136
#define X_STAGE_H  (TILE_M * LDH)                 // 17408 halves = 34816 B
#define W_STAGE_H  (R_DIM * LDH)                  // 8704 halves  = 17408 B
#define STAGE_H    (X_STAGE_H + W_STAGE_H)        // 26112 halves
#define STAGE_B    (STAGE_H * 2)                  // 52224 B
#define SMEM_TOTAL (2 * STAGE_B)                  // 104448 B (x2 CTAs ~ 209 KB)

// Pre-converted fp16 weights (8 MB static scratch — allowed)
__device__ __half g_wh[N_ADAPT * R_DIM * H_DIM];

__device__ __forceinline__ uint32_t smem_u32(const void* p) {
    uint32_t r;
    asm("{ .reg .u64 t; cvta.to.shared.u64 t, %1; cvt.u32.u64 %0, t; }"
        : "=r"(r) : "l"(p));
    return r;
}

__device__ __forceinline__ void sts64(uint32_t addr, uint32_t a, uint32_t b) {
    asm volatile("st.shared.v2.b32 [%0], {%1, %2};"
                 :: "r"(addr), "r"(a), "r"(b));
}

__device__ __forceinline__ void cp_async16(uint32_t dst, const void* src) {
    asm volatile("cp.async.cg.shared.global [%0], [%1], 16;"
                 :: "r"(dst), "l"(src) : "memory");
}
#define CP_COMMIT() asm volatile("cp.async.commit_group;" ::: "memory")
#define CP_WAIT0()  asm volatile("cp.async.wait_group 0;" ::: "memory")

// ---- kernel 1: convert all adapter weights f32 -> f16 (RN) ----------------
__global__ void convert_w_kernel(const float4* __restrict__ w) {
    int i = blockIdx.x * blockDim.x + threadIdx.x;   // one float4 each
    float4 v = w[i];
    __half2 h0 = __floats2half2_rn(v.x, v.y);
    __half2 h1 = __floats2half2_rn(v.z, v.w);
    uint2 p;
    p.x = *(const uint32_t*)&h0;
    p.y = *(const uint32_t*)&h1;
    ((uint2*)g_wh)[i] = p;
}

// ---- kernel 2: gathered GEMM, fp16 HMMA, KC=128 ---------------------------
__global__ void __launch_bounds__(NTHREADS, 2)
multilora_fp16_k128_kernel(const float* __restrict__ x,
                           const int* __restrict__ adapter_ids,
                           float* __restrict__ out) {
    extern __shared__ __align__(16) __half smem[];
    const uint32_t smem_base = smem_u32(smem);

    const int tid = threadIdx.x;
    const int wid = tid >> 5;

    const int mtile = blockIdx.x;       // 0..15
    const int b     = blockIdx.y;       // 0..31
    const int m0    = mtile * TILE_M;
    const int aid   = __ldg(adapter_ids + b);

    // ---- x producer mapping: 4096 quads / chunk over 256 threads = 16 each
    // quad i = tid + 256j: row = (tid>>5) + 8j, q = tid & 31 (16B quads)
    const int r0 = tid >> 5;            // 0..7
    const int q  = tid & 31;            // 0..31
    const float* xbase = x + ((size_t)(b * S_DIM + m0 + r0)) * H_DIM + q * 4;
    const uint32_t xoff0 = smem_base + (uint32_t)((r0 * LDH + q * 4) * 2);
    // per-j increments: gmem += 8*H_DIM floats, smem += 8*LDH*2 bytes

    // ---- w cp.async mapping: 1024 16B-copies / chunk over 256 threads = 4
    // copy i = tid + 256j: row = i>>4 (0..63), seg = i&15 (8 halves each)
    const __half* whbase = g_wh + (size_t)aid * R_DIM * H_DIM;

    // ---- consumer mapping: 8 warps, 32x32 warp tiles (4 along M, 2 along N)
    const int wm = wid >> 1;
    const int wn = wid & 1;

    wmma::fragment<wmma::accumulator, 16, 16, 16, float> acc[2][2];
    #pragma unroll
    for (int fi = 0; fi < 2; fi++)
        #pragma unroll
        for (int fj = 0; fj < 2; fj++)
            wmma::fill_fragment(acc[fi][fj], 0.0f);

    // ---- prologue: w(0) via cp.async into stage 0; x(0) into registers
    #pragma unroll
    for (int j = 0; j < 4; j++) {
        int i = tid + j * NTHREADS;
        int row = i >> 4, seg = i & 15;
        cp_async16(smem_base + (uint32_t)((X_STAGE_H + row * LDH + seg * 8) * 2),
                   whbase + (size_t)row * H_DIM + seg * 8);
    }
    CP_COMMIT();

    float4 cur[16];
    #pragma unroll
    for (int j = 0; j < 16; j++)
        cur[j] = *(const float4*)(xbase + (size_t)j * 8 * H_DIM);

    for (int kc = 0; kc < NCHUNK; kc++) {
        const int s = kc & 1;
        const uint32_t sb = smem_base + s * STAGE_B;
        __half* xs = smem + s * STAGE_H;
        __half* ws = xs + X_STAGE_H;

        // x: RN convert + STS.64 (empties cur)
        #pragma unroll
        for (int j = 0; j < 16; j++) {
            __half2 h0 = __floats2half2_rn(cur[j].x, cur[j].y);
            __half2 h1 = __floats2half2_rn(cur[j].z, cur[j].w);
            sts64(sb - smem_base + xoff0 + (uint32_t)(j * 8 * LDH * 2),
                  *(const uint32_t*)&h0, *(const uint32_t*)&h1);
        }

        // x loads for chunk kc+1 (land during barrier + 8 k-steps below)
        if (kc + 1 < NCHUNK) {
            #pragma unroll
            for (int j = 0; j < 16; j++)
                cur[j] = *(const float4*)(xbase + (size_t)j * 8 * H_DIM
                                          + (size_t)(kc + 1) * KC);
        }

        // w(kc) must be resident: only group(kc) can be pending here
        CP_WAIT0();

        // Barrier: RAW on stage s (x STS + w cp.async both visible);
        // also proves WMMA(kc-1) done on all warps -> stage s^1 writable.
        __syncthreads();

        // w(kc+1) via cp.async into stage s^1 (safe after the barrier)
        if (kc + 1 < NCHUNK) {
            const uint32_t sb1 = smem_base + (s ^ 1) * STAGE_B;
            #pragma unroll
            for (int j = 0; j < 4; j++) {
                int i = tid + j * NTHREADS;
                int row = i >> 4, seg = i & 15;
                cp_async16(sb1 + (uint32_t)((X_STAGE_H + row * LDH + seg * 8) * 2),
                           whbase + (size_t)row * H_DIM
                                  + (size_t)(kc + 1) * KC + seg * 8);
            }
        }
        CP_COMMIT();

        // compute: 8 k-steps of m16n16k16
        #pragma unroll
        for (int kk = 0; kk < KC; kk += 16) {
            wmma::fragment<wmma::matrix_a, 16, 16, 16, __half,
                           wmma::row_major> af[2];
            wmma::fragment<wmma::matrix_b, 16, 16, 16, __half,
                           wmma::col_major> bf[2];
            #pragma unroll
            for (int fi = 0; fi < 2; fi++)
                wmma::load_matrix_sync(af[fi],
                    xs + (wm * 32 + fi * 16) * LDH + kk, LDH);
            #pragma unroll
            for (int fj = 0; fj < 2; fj++)
                wmma::load_matrix_sync(bf[fj],
                    ws + (wn * 32 + fj * 16) * LDH + kk, LDH);
            #pragma unroll
            for (int fi = 0; fi < 2; fi++)
                #pragma unroll
                for (int fj = 0; fj < 2; fj++)
                    wmma::mma_sync(acc[fi][fj], af[fi], bf[fj], acc[fi][fj]);
        }
    }

    // ---- epilogue: direct store to gmem, out is [B, S, R] row-major
    float* obase = out + ((size_t)(b * S_DIM + m0 + wm * 32)) * R_DIM + wn * 32;
    #pragma unroll
    for (int fi = 0; fi < 2; fi++)
        #pragma unroll
        for (int fj = 0; fj < 2; fj++)
            wmma::store_matrix_sync(obase + (size_t)fi * 16 * R_DIM + fj * 16,
                                    acc[fi][fj], R_DIM, wmma::mem_row_major);
}

extern "C" void kernel_launch(void* const* d_in, const int* in_sizes, int n_in,
                              void* d_out, int out_size) {
    const float* x   = (const float*)d_in[0];
    const int*   ids = (const int*)d_in[1];
    const float* w   = (const float*)d_in[2];
    float* out = (float*)d_out;

    const int b = in_sizes[1];   // number of requests (32)

    // 1) convert adapter weights f32 -> f16 once per launch
    const int n4 = (N_ADAPT * R_DIM * H_DIM) / 4;    // 1,048,576 float4s
    convert_w_kernel<<<n4 / 256, 256>>>((const float4*)w);

    // 2) main gathered GEMM
    cudaFuncSetAttribute(multilora_fp16_k128_kernel,
                         cudaFuncAttributeMaxDynamicSharedMemorySize, SMEM_TOTAL);
    dim3 grid(S_DIM / TILE_M, b);
    multilora_fp16_k128_kernel<<<grid, NTHREADS, SMEM_TOTAL>>>(x, ids, out);
}

// round 11
// speedup vs baseline: 1.5019x; 1.5019x over previous
#include <cuda_runtime.h>
#include <cuda_fp16.h>
#include <mma.h>
#include <cstdint>

using namespace nvcuda;

// Problem constants
#define B_DIM      32
#define S_DIM      2048
#define H_DIM      4096
#define R_DIM      64
#define N_ADAPT    16
#define TILE_M     128
#define KC         64                  // K elements per chunk (locked from R8)
#define NCHUNK     (H_DIM / KC)        // 64
#define NTHREADS   256

// SMEM (half): row stride 72 halves = 144 B (conflict-free, ldm mult of 8)
#define LDH        72
#define X_STAGE_H  (TILE_M * LDH)                 // 9216 halves = 18432 B
#define W_STAGE_H  (R_DIM * LDH)                  // 4608 halves = 9216 B
#define STAGE_H    (X_STAGE_H + W_STAGE_H)        // 13824 halves
#define STAGE_B    (STAGE_H * 2)                  // 27648 B
#define SMEM_TOTAL (2 * STAGE_B)                  // 55296 B (x2 CTAs = 110592)

// Pre-converted fp16 weights (8 MB static scratch)
__device__ __half g_wh[N_ADAPT * R_DIM * H_DIM];

__device__ __forceinline__ uint32_t smem_u32(const void* p) {
    uint32_t r;
    asm("{ .reg .u64 t; cvta.to.shared.u64 t, %1; cvt.u32.u64 %0, t; }"
        : "=r"(r) : "l"(p));
    return r;
}

__device__ __forceinline__ void sts64(uint32_t addr, uint32_t a, uint32_t b) {
    asm volatile("st.shared.v2.b32 [%0], {%1, %2};"
                 :: "r"(addr), "r"(a), "r"(b));
}

__device__ __forceinline__ void cp_async16(uint32_t dst, const void* src) {
    asm volatile("cp.async.cg.shared.global [%0], [%1], 16;"
                 :: "r"(dst), "l"(src) : "memory");
}
#define CP_COMMIT() asm volatile("cp.async.commit_group;" ::: "memory")
#define CP_WAIT0()  asm volatile("cp.async.wait_group 0;" ::: "memory")

// ---- kernel 1: convert all adapter weights f32 -> f16 (RN) ----------------
__global__ void convert_w_kernel(const float4* __restrict__ w) {
    int i = blockIdx.x * blockDim.x + threadIdx.x;   // one float4 each
    float4 v = w[i];
    __half2 h0 = __floats2half2_rn(v.x, v.y);
    __half2 h1 = __floats2half2_rn(v.z, v.w);
    uint2 p;
    p.x = *(const uint32_t*)&h0;
    p.y = *(const uint32_t*)&h1;
    ((uint2*)g_wh)[i] = p;
}

// ---- kernel 2: gathered GEMM, fp16 HMMA, KC=64, w via cp.async ------------
__global__ void __launch_bounds__(NTHREADS, 2)
multilora_fp16_wasync_kernel(const float* __restrict__ x,
                             const int* __restrict__ adapter_ids,
                             float* __restrict__ out) {
    extern __shared__ __align__(16) __half smem[];
    const uint32_t smem_base = smem_u32(smem);

    const int tid = threadIdx.x;
    const int wid = tid >> 5;

    const int mtile = blockIdx.x;       // 0..15
    const int b     = blockIdx.y;       // 0..31
    const int m0    = mtile * TILE_M;
    const int aid   = __ldg(adapter_ids + b);

    // ---- x producer mapping: 2048 float4 quads / chunk over 256 thr = 8 each
    // quad i = tid + 256j: row = i>>4 (0..127), q = i&15
    const float* xg[8];
    uint32_t xoff[8];
    #pragma unroll
    for (int j = 0; j < 8; j++) {
        int i = tid + j * NTHREADS;
        int row = i >> 4, q = i & 15;
        xg[j]   = x + ((size_t)(b * S_DIM + m0 + row)) * H_DIM + q * 4;
        xoff[j] = (uint32_t)((row * LDH + q * 4) * 2);
    }

    // ---- w cp.async mapping: 512 16B-copies / chunk over 256 thr = 2 each
    // copy i = tid + 256j: row = i>>3 (0..63), seg = i&7 (8 halves each)
    const __half* whbase = g_wh + (size_t)aid * R_DIM * H_DIM;
    const __half* wg[2];
    uint32_t woff[2];
    #pragma unroll
    for (int j = 0; j < 2; j++) {
        int i = tid + j * NTHREADS;
        int row = i >> 3, seg = i & 7;
        wg[j]   = whbase + (size_t)row * H_DIM + seg * 8;
        woff[j] = (uint32_t)((X_STAGE_H + row * LDH + seg * 8) * 2);
    }

    // ---- consumer mapping: 8 warps, 32x32 warp tiles (4 along M, 2 along N)
    const int wm = wid >> 1;
    const int wn = wid & 1;

    wmma::fragment<wmma::accumulator, 16, 16, 16, float> acc[2][2];
    #pragma unroll
    for (int fi = 0; fi < 2; fi++)
        #pragma unroll
        for (int fj = 0; fj < 2; fj++)
            wmma::fill_fragment(acc[fi][fj], 0.0f);

    // ---- prologue: w(0) into stage 0 via cp.async; x(0) into registers
    #pragma unroll
    for (int j = 0; j < 2; j++)
        cp_async16(smem_base + woff[j], wg[j]);
    CP_COMMIT();

    float4 cur[8];
    #pragma unroll
    for (int j = 0; j < 8; j++)
        cur[j] = *(const float4*)(xg[j]);

    for (int kc = 0; kc < NCHUNK; kc++) {
        const int s = kc & 1;
        const uint32_t sb = smem_base + s * STAGE_B;
        __half* xs = smem + s * STAGE_H;
        __half* ws = xs + X_STAGE_H;

        // x: RN convert + STS.64 (empties cur)
        #pragma unroll
        for (int j = 0; j < 8; j++) {
            __half2 h0 = __floats2half2_rn(cur[j].x, cur[j].y);
            __half2 h1 = __floats2half2_rn(cur[j].z, cur[j].w);
            sts64(sb + xoff[j],
                  *(const uint32_t*)&h0, *(const uint32_t*)&h1);
        }

        // x loads for chunk kc+1 (land during barrier + 4 k-steps below)
        if (kc + 1 < NCHUNK) {
            #pragma unroll
            for (int j = 0; j < 8; j++)
                cur[j] = *(const float4*)(xg[j] + (size_t)(kc + 1) * KC);
        }

        // w(kc) must be resident (only group(kc) can still be pending)
        CP_WAIT0();

        // Barrier: RAW on stage s (x STS + w cp.async visible to all);
        // also proves WMMA(kc-1) done -> stage s^1 writable below.
        __syncthreads();

        // w(kc+1) via cp.async into stage s^1
        if (kc + 1 < NCHUNK) {
            const uint32_t sb1 = smem_base + (s ^ 1) * STAGE_B;
            #pragma unroll
            for (int j = 0; j < 2; j++)
                cp_async16(sb1 + woff[j], wg[j] + (size_t)(kc + 1) * KC);
        }
        CP_COMMIT();

        // compute: 4 k-steps of m16n16k16
        #pragma unroll
        for (int kk = 0; kk < KC; kk += 16) {
            wmma::fragment<wmma::matrix_a, 16, 16, 16, __half,
                           wmma::row_major> af[2];
            wmma::fragment<wmma::matrix_b, 16, 16, 16, __half,
                           wmma::col_major> bf[2];
            #pragma unroll
            for (int fi = 0; fi < 2; fi++)
                wmma::load_matrix_sync(af[fi],
                    xs + (wm * 32 + fi * 16) * LDH + kk, LDH);
            #pragma unroll
            for (int fj = 0; fj < 2; fj++)
                wmma::load_matrix_sync(bf[fj],
                    ws + (wn * 32 + fj * 16) * LDH + kk, LDH);
            #pragma unroll
            for (int fi = 0; fi < 2; fi++)
                #pragma unroll
                for (int fj = 0; fj < 2; fj++)
                    wmma::mma_sync(acc[fi][fj], af[fi], bf[fj], acc[fi][fj]);
        }
    }

    // ---- epilogue: direct store to gmem, out is [B, S, R] row-major
    float* obase = out + ((size_t)(b * S_DIM + m0 + wm * 32)) * R_DIM + wn * 32;
    #pragma unroll
    for (int fi = 0; fi < 2; fi++)
        #pragma unroll
        for (int fj = 0; fj < 2; fj++)
            wmma::store_matrix_sync(obase + (size_t)fi * 16 * R_DIM + fj * 16,
                                    acc[fi][fj], R_DIM, wmma::mem_row_major);
}

extern "C" void kernel_launch(void* const* d_in, const int* in_sizes, int n_in,
                              void* d_out, int out_size) {
    const float* x   = (const float*)d_in[0];
    const int*   ids = (const int*)d_in[1];
    const float* w   = (const float*)d_in[2];
    float* out = (float*)d_out;

    const int b = in_sizes[1];   // number of requests (32)

    // 1) convert adapter weights f32 -> f16 once per launch (~4 us)
    const int n4 = (N_ADAPT * R_DIM * H_DIM) / 4;    // 1,048,576 float4s
    convert_w_kernel<<<n4 / 256, 256>>>((const float4*)w);

    // 2) main gathered GEMM
    cudaFuncSetAttribute(multilora_fp16_wasync_kernel,
                         cudaFuncAttributeMaxDynamicSharedMemorySize, SMEM_TOTAL);
    dim3 grid(S_DIM / TILE_M, b);
    multilora_fp16_wasync_kernel<<<grid, NTHREADS, SMEM_TOTAL>>>(x, ids, out);
}